// round 9
// baseline (speedup 1.0000x reference)
#include <cuda_runtime.h>

#define FF 16
#define SS 28
#define B_ 1024

// Effective affine map: out[b,co,d,h,w] = sum_i E[co,i,fd,fh,fw]*x[b,i] + B[co,fd,fh,fw]
__device__ float g_E[3 * 3 * 5 * 5 * 5];   // 1125
__device__ float g_B[3 * 5 * 5 * 5];       // 375

__device__ __forceinline__ int fcls(int p, int n) {
    int c = 2;
    if (p == 0)          c = 0;
    else if (p == 1)     c = 1;
    else if (p == n - 1) c = 4;
    else if (p == n - 2) c = 3;
    return c;
}

// conv1 3-class mask: class 0 drops tap k=0, class 2 drops tap k=2.
__device__ __forceinline__ float mask3(int c, int k) {
    return ((c == 0 && k == 0) || (c == 2 && k == 2)) ? 0.f : 1.f;
}

// ---------------------------------------------------------------------------
// Precompute E and Beff. 9 blocks x 352 threads:
//  - one S1 entry per thread (no serial multi-entry loops)
//  - E contraction with 4 independent accumulators (chain 432 -> 108)
// ---------------------------------------------------------------------------
__global__ void __launch_bounds__(352) precompute_kernel(
        const float* __restrict__ w1, const float* __restrict__ b1,
        const float* __restrict__ w2, const float* __restrict__ b2) {
    __shared__ float sw1[324], sw2[324], S1[324];
    __shared__ float sb1[4], sb2[3];
    const int t   = threadIdx.x;
    const int blk = blockIdx.x;

    if (t < 324) { sw1[t] = w1[t]; sw2[t] = w2[t]; }
    if (t < 4) sb1[t] = b1[t];
    if (t < 3) sb2[t] = b2[t];
    __syncthreads();

    // S1[o][i][cd*9+ch*3+cw]: one entry per thread, branch-free masked sum.
    if (t < 324) {
        int cw = t % 3, ch = (t / 3) % 3, cd = (t / 9) % 3;
        int base = (t / 27) * 27;
        float s = 0.f;
#pragma unroll
        for (int kd = 0; kd < 3; kd++) {
            float md = mask3(cd, kd);
#pragma unroll
            for (int kh = 0; kh < 3; kh++) {
                float mh = md * mask3(ch, kh);
#pragma unroll
                for (int kw = 0; kw < 3; kw++)
                    s += mh * mask3(cw, kw) * sw1[base + kd * 9 + kh * 3 + kw];
            }
        }
        S1[t] = s;
    }
    __syncthreads();

    if (t < 125) {
        const int fw = t % 5, fh = (t / 5) % 5, fd = t / 25;

        float vaD[3], vaH[3], vaW[3];
        int   nbD[3], nbH[3], nbW[3];
#pragma unroll
        for (int tt = 0; tt < 3; tt++) {
            vaD[tt] = ((fd == 0 && tt == 0) || (fd == 4 && tt == 2)) ? 0.f : 1.f;
            vaH[tt] = ((fh == 0 && tt == 0) || (fh == 4 && tt == 2)) ? 0.f : 1.f;
            vaW[tt] = ((fw == 0 && tt == 0) || (fw == 4 && tt == 2)) ? 0.f : 1.f;
            int pd = fd + tt - 1; nbD[tt] = (pd == 0) ? 0 : (pd == 4) ? 2 : 1;
            int ph = fh + tt - 1; nbH[tt] = (ph == 0) ? 0 : (ph == 4) ? 2 : 1;
            int pw = fw + tt - 1; nbW[tt] = (pw == 0) ? 0 : (pw == 4) ? 2 : 1;
        }

        // E slice: element e = blk*125 + t;  i = blk%3, co = blk/3.
        {
            const int i  = blk % 3;
            const int co = blk / 3;
            float a0 = 0.f, a1 = 0.f, a2 = 0.f, a3 = 0.f;  // per-o accumulators
#pragma unroll
            for (int td = 0; td < 3; td++) {
                float cD = vaD[td]; int cd9 = nbD[td] * 9;
#pragma unroll
                for (int th = 0; th < 3; th++) {
                    float cH = cD * vaH[th]; int ch3 = cd9 + nbH[th] * 3;
#pragma unroll
                    for (int tw = 0; tw < 3; tw++) {
                        float coef = cH * vaW[tw];
                        int w2i = co * 108 + td * 9 + th * 3 + tw;   // + o*27
                        int s1i = i * 27 + ch3 + nbW[tw];            // + o*81
                        a0 += coef * sw2[w2i      ] * S1[s1i      ];
                        a1 += coef * sw2[w2i +  27] * S1[s1i +  81];
                        a2 += coef * sw2[w2i +  54] * S1[s1i + 162];
                        a3 += coef * sw2[w2i +  81] * S1[s1i + 243];
                    }
                }
            }
            g_E[blk * 125 + t] = (a0 + a1) + (a2 + a3);
        }

        // B: blocks 0-2 own co = blk.
        if (blk < 3) {
            const int co = blk;
            float s = sb2[co];
#pragma unroll
            for (int o = 0; o < 4; o++) {
                float ws = 0.f;
#pragma unroll
                for (int td = 0; td < 3; td++) {
#pragma unroll
                    for (int th = 0; th < 3; th++) {
                        float cH = vaD[td] * vaH[th];
#pragma unroll
                        for (int tw = 0; tw < 3; tw++)
                            ws += cH * vaW[tw] * sw2[co * 108 + o * 27 + td * 9 + th * 3 + tw];
                    }
                }
                s += sb1[o] * ws;
            }
            g_B[blk * 125 + t] = s;
        }
    }
}

// ---------------------------------------------------------------------------
// Expand: 2 blocks per batch element (d-halves). Build v[375] in smem, then
// each of 196 threads REGISTER-CACHES its 9 distinct float4 values
// (3 co x 3 d-classes of this half; 36 LDS) and fires 48 dependency-free
// STG.128s back-to-back.
// ---------------------------------------------------------------------------
__global__ void __launch_bounds__(224) expand_kernel(const float* __restrict__ x,
                                                     float4* __restrict__ out) {
    __shared__ float v[375];           // v[co*125 + fd*25 + fh*5 + fw]
    const int blk = blockIdx.x;
    const int b   = blk >> 1;
    const int p   = blk & 1;           // d-half: 0 -> d 0..7, 1 -> d 8..15
    const int tid = threadIdx.x;

    float x0 = __ldg(&x[b * 3 + 0]);
    float x1 = __ldg(&x[b * 3 + 1]);
    float x2 = __ldg(&x[b * 3 + 2]);
    for (int e = tid; e < 375; e += 224) {
        int co = e / 125;
        int sp = e - co * 125;
        int eb = co * 375 + sp;        // i stride = 125 in g_E
        v[e] = g_B[e] + x0 * g_E[eb] + x1 * g_E[eb + 125] + x2 * g_E[eb + 250];
    }
    __syncthreads();

    if (tid < 196) {
        int h  = tid / 7;
        int w4 = tid - h * 7;
        int fh = fcls(h, SS);
        int i0 = (w4 == 0) ? 0 : 2;
        int i1 = (w4 == 0) ? 1 : 2;
        int i2 = (w4 == 6) ? 3 : 2;
        int i3 = (w4 == 6) ? 4 : 2;
        int base = fh * 5;
        int fd0  = p ? 2 : 0;          // global class of local index 0

        // Register-cache the 9 distinct values (co x local d-class).
        float4 val[9];
#pragma unroll
        for (int co = 0; co < 3; co++) {
#pragma unroll
            for (int g = 0; g < 3; g++) {
                const float* vv = v + co * 125 + (fd0 + g) * 25 + base;
                val[co * 3 + g] = make_float4(vv[i0], vv[i1], vv[i2], vv[i3]);
            }
        }

        // d -> LOCAL class index within this half.
        const int dloc0[8] = {0,1,2,2,2,2,2,2};   // classes 0,1,2
        const int dloc1[8] = {0,0,0,0,0,0,1,2};   // classes 2,3,4

        float4* op = out + (size_t)b * (3 * FF * 196) + (size_t)p * (8 * 196) + tid;
#pragma unroll
        for (int co = 0; co < 3; co++) {
#pragma unroll
            for (int dd = 0; dd < 8; dd++) {
                int g = p ? dloc1[dd] : dloc0[dd];
                op[(co * FF + dd) * 196] = val[co * 3 + g];
            }
        }
    }
}

extern "C" void kernel_launch(void* const* d_in, const int* in_sizes, int n_in,
                              void* d_out, int out_size) {
    const float* x  = (const float*)d_in[0];
    const float* w1 = (const float*)d_in[1];
    const float* b1 = (const float*)d_in[2];
    const float* w2 = (const float*)d_in[3];
    const float* b2 = (const float*)d_in[4];

    precompute_kernel<<<9, 352>>>(w1, b1, w2, b2);
    expand_kernel<<<B_ * 2, 224>>>(x, (float4*)d_out);
}

// round 10
// speedup vs baseline: 1.5635x; 1.5635x over previous
#include <cuda_runtime.h>

#define FF 16
#define SS 28
#define B_ 1024

// Effective affine map: out[b,co,d,h,w] = sum_i E[co,i,fd,fh,fw]*x[b,i] + B[co,fd,fh,fw]
__device__ float g_E[3 * 3 * 5 * 5 * 5];   // 1125
__device__ float g_B[3 * 5 * 5 * 5];       // 375

__device__ __forceinline__ int fcls(int p, int n) {
    int c = 2;
    if (p == 0)          c = 0;
    else if (p == 1)     c = 1;
    else if (p == n - 1) c = 4;
    else if (p == n - 2) c = 3;
    return c;
}

// conv1 3-class mask: class 0 drops tap k=0, class 2 drops tap k=2.
__device__ __forceinline__ float mask3(int c, int k) {
    return ((c == 0 && k == 0) || (c == 2 && k == 2)) ? 0.f : 1.f;
}

// ---------------------------------------------------------------------------
// Precompute E and Beff. 9 blocks x 352 threads, one S1 entry / one E element
// per thread, 4 independent accumulators. Signals PDL completion after its
// global stores so the dependent expand grid can proceed.
// ---------------------------------------------------------------------------
__global__ void __launch_bounds__(352) precompute_kernel(
        const float* __restrict__ w1, const float* __restrict__ b1,
        const float* __restrict__ w2, const float* __restrict__ b2) {
    __shared__ float sw1[324], sw2[324], S1[324];
    __shared__ float sb1[4], sb2[3];
    const int t   = threadIdx.x;
    const int blk = blockIdx.x;

    if (t < 324) { sw1[t] = w1[t]; sw2[t] = w2[t]; }
    if (t < 4) sb1[t] = b1[t];
    if (t < 3) sb2[t] = b2[t];
    __syncthreads();

    if (t < 324) {
        int cw = t % 3, ch = (t / 3) % 3, cd = (t / 9) % 3;
        int base = (t / 27) * 27;
        float s = 0.f;
#pragma unroll
        for (int kd = 0; kd < 3; kd++) {
            float md = mask3(cd, kd);
#pragma unroll
            for (int kh = 0; kh < 3; kh++) {
                float mh = md * mask3(ch, kh);
#pragma unroll
                for (int kw = 0; kw < 3; kw++)
                    s += mh * mask3(cw, kw) * sw1[base + kd * 9 + kh * 3 + kw];
            }
        }
        S1[t] = s;
    }
    __syncthreads();

    if (t < 125) {
        const int fw = t % 5, fh = (t / 5) % 5, fd = t / 25;

        float vaD[3], vaH[3], vaW[3];
        int   nbD[3], nbH[3], nbW[3];
#pragma unroll
        for (int tt = 0; tt < 3; tt++) {
            vaD[tt] = ((fd == 0 && tt == 0) || (fd == 4 && tt == 2)) ? 0.f : 1.f;
            vaH[tt] = ((fh == 0 && tt == 0) || (fh == 4 && tt == 2)) ? 0.f : 1.f;
            vaW[tt] = ((fw == 0 && tt == 0) || (fw == 4 && tt == 2)) ? 0.f : 1.f;
            int pd = fd + tt - 1; nbD[tt] = (pd == 0) ? 0 : (pd == 4) ? 2 : 1;
            int ph = fh + tt - 1; nbH[tt] = (ph == 0) ? 0 : (ph == 4) ? 2 : 1;
            int pw = fw + tt - 1; nbW[tt] = (pw == 0) ? 0 : (pw == 4) ? 2 : 1;
        }

        {
            const int i  = blk % 3;
            const int co = blk / 3;
            float a0 = 0.f, a1 = 0.f, a2 = 0.f, a3 = 0.f;
#pragma unroll
            for (int td = 0; td < 3; td++) {
                float cD = vaD[td]; int cd9 = nbD[td] * 9;
#pragma unroll
                for (int th = 0; th < 3; th++) {
                    float cH = cD * vaH[th]; int ch3 = cd9 + nbH[th] * 3;
#pragma unroll
                    for (int tw = 0; tw < 3; tw++) {
                        float coef = cH * vaW[tw];
                        int w2i = co * 108 + td * 9 + th * 3 + tw;   // + o*27
                        int s1i = i * 27 + ch3 + nbW[tw];            // + o*81
                        a0 += coef * sw2[w2i      ] * S1[s1i      ];
                        a1 += coef * sw2[w2i +  27] * S1[s1i +  81];
                        a2 += coef * sw2[w2i +  54] * S1[s1i + 162];
                        a3 += coef * sw2[w2i +  81] * S1[s1i + 243];
                    }
                }
            }
            g_E[blk * 125 + t] = (a0 + a1) + (a2 + a3);
        }

        if (blk < 3) {
            const int co = blk;
            float s = sb2[co];
#pragma unroll
            for (int o = 0; o < 4; o++) {
                float ws = 0.f;
#pragma unroll
                for (int td = 0; td < 3; td++) {
#pragma unroll
                    for (int th = 0; th < 3; th++) {
                        float cH = vaD[td] * vaH[th];
#pragma unroll
                        for (int tw = 0; tw < 3; tw++)
                            ws += cH * vaW[tw] * sw2[co * 108 + o * 27 + td * 9 + th * 3 + tw];
                    }
                }
                s += sb1[o] * ws;
            }
            g_B[blk * 125 + t] = s;
        }
    }

    // Make table stores visible, then release the dependent (expand) grid.
    __threadfence();
    asm volatile("griddepcontrol.launch_dependents;" ::: "memory");
}

// ---------------------------------------------------------------------------
// Expand (exact R8 26.5us body + PDL wait): 2 blocks per batch element.
// Launches overlapped with precompute; waits on griddepcontrol only right
// before reading g_E/g_B.
// ---------------------------------------------------------------------------
__global__ void __launch_bounds__(224) expand_kernel(const float* __restrict__ x,
                                                     float4* __restrict__ out) {
    __shared__ float v[375];           // v[co*125 + fd*25 + fh*5 + fw]
    const int blk = blockIdx.x;
    const int b   = blk >> 1;
    const int p   = blk & 1;           // d-half: 0 -> d 0..7, 1 -> d 8..15
    const int tid = threadIdx.x;

    // Input x is independent of precompute — load before the PDL wait.
    float x0 = __ldg(&x[b * 3 + 0]);
    float x1 = __ldg(&x[b * 3 + 1]);
    float x2 = __ldg(&x[b * 3 + 2]);

    // Block until the precompute grid has published g_E / g_B.
    asm volatile("griddepcontrol.wait;" ::: "memory");

    for (int e = tid; e < 375; e += 224) {
        int co = e / 125;
        int sp = e - co * 125;
        int eb = co * 375 + sp;        // i stride = 125 in g_E
        v[e] = g_B[e] + x0 * g_E[eb] + x1 * g_E[eb + 125] + x2 * g_E[eb + 250];
    }
    __syncthreads();

    if (tid < 196) {
        int h  = tid / 7;
        int w4 = tid - h * 7;
        int fh = fcls(h, SS);
        int i0 = (w4 == 0) ? 0 : 2;
        int i1 = (w4 == 0) ? 1 : 2;
        int i2 = (w4 == 6) ? 3 : 2;
        int i3 = (w4 == 6) ? 4 : 2;
        int base = fh * 5;

        const int dcls0[8] = {0,1,2,2,2,2,2,2};
        const int dcls1[8] = {2,2,2,2,2,2,3,4};

        float4* op = out + (size_t)b * (3 * FF * 196) + (size_t)p * (8 * 196) + tid;
#pragma unroll
        for (int co = 0; co < 3; co++) {
#pragma unroll
            for (int dd = 0; dd < 8; dd++) {
                int fd = p ? dcls1[dd] : dcls0[dd];
                const float* vv = v + co * 125 + fd * 25 + base;
                float4 o4 = make_float4(vv[i0], vv[i1], vv[i2], vv[i3]);
                op[(co * FF + dd) * 196] = o4;
            }
        }
    }
}

extern "C" void kernel_launch(void* const* d_in, const int* in_sizes, int n_in,
                              void* d_out, int out_size) {
    const float* x  = (const float*)d_in[0];
    const float* w1 = (const float*)d_in[1];
    const float* b1 = (const float*)d_in[2];
    const float* w2 = (const float*)d_in[3];
    const float* b2 = (const float*)d_in[4];

    precompute_kernel<<<9, 352>>>(w1, b1, w2, b2);

    // Expand launched with Programmatic Stream Serialization: it may begin
    // (prologue + x loads) while precompute drains; griddepcontrol.wait in
    // the kernel enforces the real dependency on g_E/g_B.
    cudaLaunchConfig_t cfg = {};
    cfg.gridDim  = dim3(B_ * 2, 1, 1);
    cfg.blockDim = dim3(224, 1, 1);
    cudaLaunchAttribute attr[1];
    attr[0].id = cudaLaunchAttributeProgrammaticStreamSerialization;
    attr[0].val.programmaticStreamSerializationAllowed = 1;
    cfg.attrs    = attr;
    cfg.numAttrs = 1;
    cudaLaunchKernelEx(&cfg, expand_kernel, x, (float4*)d_out);
}